// round 12
// baseline (speedup 1.0000x reference)
#include <cuda_runtime.h>

// Problem constants
#define TSEQ 1024
#define NB   32      // batch
#define ID   512     // input dim
#define HD   512     // hidden dim
#define GD   2048    // 4*H gate rows
#define NBLK_DIR 64  // persistent blocks per direction (8 hidden units each)
#define REC_THREADS 256

typedef unsigned long long ull;

// Scratch (device globals: no runtime allocation allowed)
__device__ float g_xw[(size_t)TSEQ * GD * NB];   // [t][g][b], 256MB
__device__ float g_hbuf[2][2][HD * NB];          // [dir][ping][u*32 + b]
__device__ unsigned g_barcnt[2];   // flat barrier arrival counters (monotonic)
__device__ unsigned g_bargen[2];   // generation flags (monotonic)

// ---------------------------------------------------------------------------
// packed fp32x2 ops (Blackwell)
// ---------------------------------------------------------------------------
__device__ __forceinline__ void ffma2(ull& d, ull a, ull b) {
    asm("fma.rn.f32x2 %0, %1, %2, %0;" : "+l"(d) : "l"(a), "l"(b));
}
__device__ __forceinline__ ull addf2(ull a, ull b) {
    ull r;
    asm("add.rn.f32x2 %0, %1, %2;" : "=l"(r) : "l"(a), "l"(b));
    return r;
}
__device__ __forceinline__ ull dup2(float x) {
    ull r;
    asm("mov.b64 %0, {%1, %1};" : "=l"(r) : "f"(x));
    return r;
}
__device__ __forceinline__ float pairsum(ull v) {
    float2 f = *reinterpret_cast<float2*>(&v);
    return f.x + f.y;
}

__device__ __forceinline__ unsigned atom_add_acqrel(unsigned* p, unsigned v) {
    unsigned old;
    asm volatile("atom.acq_rel.gpu.add.u32 %0, [%1], %2;"
                 : "=r"(old) : "l"(p), "r"(v) : "memory");
    return old;
}
__device__ __forceinline__ unsigned ld_acquire(const unsigned* p) {
    unsigned v;
    asm volatile("ld.acquire.gpu.u32 %0, [%1];" : "=r"(v) : "l"(p) : "memory");
    return v;
}
__device__ __forceinline__ void st_release(unsigned* p, unsigned v) {
    asm volatile("st.release.gpu.u32 [%0], %1;" :: "l"(p), "r"(v) : "memory");
}

__device__ __forceinline__ float sigf(float x) {
    return __fdividef(1.f, 1.f + __expf(-x));
}
__device__ __forceinline__ float tanhfast(float x) {
    return __fdividef(2.f, 1.f + __expf(-2.f * x)) - 1.f;
}

// ---------------------------------------------------------------------------
// xw[t][g][b] = sum_i x[t][b][i] * W_ih[g][i] + (b_ih[g] + b_hh[g])
// Also zeroes its 2KB slice of d_out.
// R12: xs stride 34 + LDS.64 reads -> 2-way (optimal) instead of 4-way conflict.
// ---------------------------------------------------------------------------
__global__ __launch_bounds__(256) void xw_gemm(
    const float* __restrict__ x,
    const float* __restrict__ Wih,
    const float* __restrict__ bih,
    const float* __restrict__ bhh,
    float4* __restrict__ out4)
{
    __shared__ float xs[NB * 34];   // [b][kk], stride 34 (8B aligned per b-row)
    __shared__ float ws[64 * 32];   // [g_local][kk]

    if (threadIdx.x < 128)
        out4[(size_t)blockIdx.x * 128 + threadIdx.x] = make_float4(0.f, 0.f, 0.f, 0.f);

    int t   = blockIdx.x >> 5;
    int g0  = (blockIdx.x & 31) << 6;
    int tid = threadIdx.x;
    int gg  = tid >> 5;
    int b   = tid & 31;

    ull acc[8];
#pragma unroll
    for (int j = 0; j < 8; j++) acc[j] = 0ull;

    const float* xt = x + (size_t)t * NB * ID;

    for (int k0 = 0; k0 < ID; k0 += 32) {
#pragma unroll
        for (int r = 0; r < 4; r++) {
            int bl = (tid >> 5) + (r << 3);
            int kk = tid & 31;
            xs[bl * 34 + kk] = xt[bl * ID + k0 + kk];
        }
#pragma unroll
        for (int r = 0; r < 8; r++) {
            int gl = (tid >> 5) + (r << 3);
            int kk = tid & 31;
            ws[gl * 32 + kk] = Wih[(size_t)(g0 + gl) * ID + k0 + kk];
        }
        __syncthreads();

#pragma unroll
        for (int kk = 0; kk < 32; kk += 4) {
            const ull* xu = (const ull*)&xs[b * 34 + kk];   // 8B aligned (34b+kk even)
            ull x01 = xu[0];
            ull x23 = xu[1];
#pragma unroll
            for (int j = 0; j < 8; j++) {
                ulonglong2 wv = *(const ulonglong2*)&ws[(gg * 8 + j) * 32 + kk];
                ffma2(acc[j], x01, wv.x);
                ffma2(acc[j], x23, wv.y);
            }
        }
        __syncthreads();
    }

    float* outp = g_xw + (size_t)t * GD * NB;
#pragma unroll
    for (int j = 0; j < 8; j++) {
        int g = g0 + gg * 8 + j;
        outp[g * NB + b] = pairsum(acc[j]) + bih[g] + bhh[g];
    }
}

// ---------------------------------------------------------------------------
// Flat per-direction barrier (R8-proven), split into arrive / per-warp wait.
// All counters monotonic (graph-replay safe). Release sequence: acq_rel RMWs
// on g_barcnt chain to the final st.release on g_bargen; waiters ld.acquire.
// ---------------------------------------------------------------------------
__device__ __forceinline__ void bar_arrive_flat(int dir, unsigned gen) {
    unsigned old = atom_add_acqrel(&g_barcnt[dir], 1u);
    if (old == gen * (unsigned)NBLK_DIR + (NBLK_DIR - 1))
        st_release(&g_bargen[dir], gen + 1u);
}
__device__ __forceinline__ void bar_wait_flat(int dir, unsigned gen) {
    while ((int)(ld_acquire(&g_bargen[dir]) - (gen + 1u)) < 0) { }
}

// ---------------------------------------------------------------------------
// Persistent bidirectional zoneout-LSTM recurrence (R8 compute structure).
// 128 blocks: 0..63 fwd, 64..127 bwd. Block: 8 hidden units (32 gate rows) x 32 b.
// R12 deltas vs R8: per-warp wake (lane0 polls, __syncwarp), xw prefetch
// issued BEFORE the wait, c/h_old in registers.
// ---------------------------------------------------------------------------
__global__ __launch_bounds__(REC_THREADS, 1) void lstm_rec(
    const float* __restrict__ Whh, float* __restrict__ out)
{
    extern __shared__ float smem[];
    float* Wt   = smem;             // 64KB: Wt[k*32 + row]
    float* Hs   = smem + 16384;     // 64KB: Hs[u*32 + b]
    float* gbuf = smem + 32768;     // 34KB: gbuf[w*1088 + row*34 + b]

    int bid  = blockIdx.x;
    int dir  = bid >> 6;
    int j0   = (bid & 63) << 3;
    int tid  = threadIdx.x;
    int w    = tid >> 5;
    int lane = tid & 31;
    int ks0  = lane >> 4;
    int rg   = (lane >> 2) & 3;
    int bg   = lane & 3;
    int u_l  = w;               // cell phase: unit-local 0..7
    int gu   = j0 + u_l;

    // Stage W_hh once: Wt[k*32 + row], row -> global W row (row>>3)*512 + j0 + (row&7)
#pragma unroll 4
    for (int i = 0; i < 64; i++) {
        int idx = tid + (i << 8);
        int row = idx >> 9;
        int k   = idx & 511;
        int gr  = ((row >> 3) << 9) + j0 + (row & 7);
        Wt[k * 32 + row] = Whh[(size_t)gr * HD + k];
    }

    // init h(step 0) = 0 (own units); c and h_old live in registers
    float c_reg = 0.f;
    float h_reg = 0.f;
    g_hbuf[dir][0][gu * 32 + lane] = 0.f;

    unsigned gen = ld_acquire(&g_bargen[dir]);   // monotonic base (replay-safe)
    __syncthreads();
    if (tid == 0) bar_arrive_flat(dir, gen);     // publish h0

    const float4* W4 = (const float4*)Wt;
    const float4* H4 = (const float4*)Hs;
    const int kbeg = (w << 6) + (ks0 << 5);

    for (int s = 0; s < TSEQ; s++) {
        int t = dir ? (TSEQ - 1 - s) : s;
        const float* xw_t = g_xw + (size_t)t * GD * NB;

        // prefetch xw BEFORE the wait: DRAM latency hidden under the spin
        float xg0 = xw_t[(0 * HD + gu) * NB + lane];
        float xg1 = xw_t[(1 * HD + gu) * NB + lane];
        float xg2 = xw_t[(2 * HD + gu) * NB + lane];
        float xg3 = xw_t[(3 * HD + gu) * NB + lane];

        // per-warp wake: each warp proceeds to its own h copy independently
        if (lane == 0) bar_wait_flat(dir, gen);
        __syncwarp();
        gen++;

        // per-warp copy of its own h k-range [64w, 64w+64): float4 [512w, 512w+512)
        {
            const float4* hsrc = (const float4*)g_hbuf[dir][s & 1];
            float4* hdst = (float4*)Hs;
#pragma unroll
            for (int i = 0; i < 16; i++) {
                int idx = (w << 9) + (i << 5) + lane;
                hdst[idx] = __ldcg(&hsrc[idx]);
            }
            __syncwarp();   // order cross-lane STS -> LDS within this warp
        }

        // GEMV: 8 rows x 4 batch-pairs per lane over 32 k
        ull acc[8][4];
#pragma unroll
        for (int i = 0; i < 8; i++)
#pragma unroll
            for (int j = 0; j < 4; j++) acc[i][j] = 0ull;

#pragma unroll 4
        for (int kk = 0; kk < 32; kk++) {
            int k = kbeg + kk;
            float4 wA = W4[(k << 3) + (rg << 1)];       // rows 8rg..8rg+3
            float4 wB = W4[(k << 3) + (rg << 1) + 1];   // rows 8rg+4..8rg+7
            ulonglong2 hA = *(const ulonglong2*)&H4[(k << 3) + (bg << 1)];
            ulonglong2 hB = *(const ulonglong2*)&H4[(k << 3) + (bg << 1) + 1];
            float wf[8] = {wA.x, wA.y, wA.z, wA.w, wB.x, wB.y, wB.z, wB.w};
#pragma unroll
            for (int i = 0; i < 8; i++) {
                ull wd = dup2(wf[i]);
                ffma2(acc[i][0], wd, hA.x);
                ffma2(acc[i][1], wd, hA.y);
                ffma2(acc[i][2], wd, hB.x);
                ffma2(acc[i][3], wd, hB.y);
            }
        }

        // fold k-halves + store: STATIC indices only (R7 lesson)
        {
            float* gp0 = gbuf + w * 1088 + (bg << 3) + (ks0 << 2);
#pragma unroll
            for (int i = 0; i < 8; i++) {
                ull s0 = ks0 ? acc[i][0] : acc[i][2];
                ull s1 = ks0 ? acc[i][1] : acc[i][3];
                ull r0 = __shfl_xor_sync(0xFFFFFFFFu, s0, 16);
                ull r1 = __shfl_xor_sync(0xFFFFFFFFu, s1, 16);
                ull k0 = ks0 ? acc[i][2] : acc[i][0];
                ull k1 = ks0 ? acc[i][3] : acc[i][1];
                ull v0 = addf2(k0, r0);
                ull v1 = addf2(k1, r1);
                float* gp = gp0 + ((rg << 3) + i) * 34;
                *(ull*)gp = v0;
                *(ull*)(gp + 2) = v1;
            }
        }
        __syncthreads();

        // cell update: thread = (unit u_l = w, batch lane); 8 partial sets per gate
        {
            int b = lane;
            float iv = xg0, fv = xg1, gv = xg2, ov = xg3;
#pragma unroll
            for (int sw = 0; sw < 8; sw++) {
                const float* gp = gbuf + sw * 1088 + b;
                iv += gp[(0 * 8 + u_l) * 34];
                fv += gp[(1 * 8 + u_l) * 34];
                gv += gp[(2 * 8 + u_l) * 34];
                ov += gp[(3 * 8 + u_l) * 34];
            }
            iv = sigf(iv);
            fv = sigf(fv);
            gv = tanhfast(gv);
            ov = sigf(ov);
            float c_new = fv * c_reg + iv * gv;
            float h_new = ov * tanhfast(c_new);
            c_reg = 0.9f * c_new + 0.1f * c_reg;
            float h_bl = 0.9f * h_new + 0.1f * h_reg;
            h_reg = h_bl;
            g_hbuf[dir][(s + 1) & 1][gu * 32 + lane] = h_bl;
            // fire-and-forget global add; exactly two commutative fp32 adds
            // per output element -> deterministic
            atomicAdd(&out[(size_t)t * (NB * HD) + lane * HD + gu], h_bl);
        }

        // publish h_{s+1}
        __syncthreads();
        if (tid == 0) bar_arrive_flat(dir, gen);
    }
}

// ---------------------------------------------------------------------------
extern "C" void kernel_launch(void* const* d_in, const int* in_sizes, int n_in,
                              void* d_out, int out_size) {
    const float* x   = (const float*)d_in[0];
    const float* Wih = (const float*)d_in[1];
    const float* Whh = (const float*)d_in[2];
    const float* bih = (const float*)d_in[3];
    const float* bhh = (const float*)d_in[4];
    float* out = (float*)d_out;

    const int rec_smem = (16384 + 16384 + 8 * 1088) * (int)sizeof(float); // 165888 B
    cudaFuncSetAttribute(lstm_rec, cudaFuncAttributeMaxDynamicSharedMemorySize, rec_smem);

    xw_gemm<<<TSEQ * 32, 256>>>(x, Wih, bih, bhh, (float4*)out);
    lstm_rec<<<2 * NBLK_DIR, REC_THREADS, rec_smem>>>(Whh, out);
}

// round 13
// speedup vs baseline: 1.9084x; 1.9084x over previous
#include <cuda_runtime.h>

// Problem constants
#define TSEQ 1024
#define NB   32      // batch
#define ID   512     // input dim
#define HD   512     // hidden dim
#define GD   2048    // 4*H gate rows
#define NBLK_DIR 64  // persistent blocks per direction (8 hidden units each)
#define REC_THREADS 256

typedef unsigned long long ull;

// Scratch (device globals: no runtime allocation allowed)
__device__ float g_xw[(size_t)TSEQ * GD * NB];   // [t][g][b], 256MB
__device__ float g_hbuf[2][2][HD * NB];          // [dir][ping][u*32 + b]
__device__ unsigned g_barcnt[2];   // flat barrier arrival counters (monotonic)

// ---------------------------------------------------------------------------
// packed fp32x2 ops (Blackwell)
// ---------------------------------------------------------------------------
__device__ __forceinline__ void ffma2(ull& d, ull a, ull b) {
    asm("fma.rn.f32x2 %0, %1, %2, %0;" : "+l"(d) : "l"(a), "l"(b));
}
__device__ __forceinline__ ull addf2(ull a, ull b) {
    ull r;
    asm("add.rn.f32x2 %0, %1, %2;" : "=l"(r) : "l"(a), "l"(b));
    return r;
}
__device__ __forceinline__ ull dup2(float x) {
    ull r;
    asm("mov.b64 %0, {%1, %1};" : "=l"(r) : "f"(x));
    return r;
}
__device__ __forceinline__ float pairsum(ull v) {
    float2 f = *reinterpret_cast<float2*>(&v);
    return f.x + f.y;
}

__device__ __forceinline__ unsigned ld_acquire(const unsigned* p) {
    unsigned v;
    asm volatile("ld.acquire.gpu.u32 %0, [%1];" : "=r"(v) : "l"(p) : "memory");
    return v;
}

__device__ __forceinline__ float sigf(float x) {
    return __fdividef(1.f, 1.f + __expf(-x));
}
__device__ __forceinline__ float tanhfast(float x) {
    return __fdividef(2.f, 1.f + __expf(-2.f * x)) - 1.f;
}

// ---------------------------------------------------------------------------
// Flat per-direction barrier, counter-only:
//   arrive: red.release (no return value -> arriver never stalls on L2 RT)
//   wait:   ld.acquire poll on the SAME counter (no separate release flag hop)
// Counter is monotonic across graph replays; base recovered by flooring to a
// multiple of NBLK_DIR (valid: when a block reads it, fewer than NBLK_DIR
// arrivals of the current launch can have happened — its own is missing).
// ---------------------------------------------------------------------------
__device__ __forceinline__ void bar_arrive_red(int dir) {
    asm volatile("red.release.gpu.global.add.u32 [%0], %1;"
                 :: "l"(&g_barcnt[dir]), "r"(1u) : "memory");
}
__device__ __forceinline__ void bar_wait_cnt(int dir, unsigned target) {
    while ((int)(ld_acquire(&g_barcnt[dir]) - target) < 0) { }
}

// ---------------------------------------------------------------------------
// xw[t][g][b] = sum_i x[t][b][i] * W_ih[g][i] + (b_ih[g] + b_hh[g])
// Also zeroes its 2KB slice of d_out.
// xs stride 34 + LDS.64 reads -> 2-way (optimal) instead of 4-way conflicts.
// ---------------------------------------------------------------------------
__global__ __launch_bounds__(256) void xw_gemm(
    const float* __restrict__ x,
    const float* __restrict__ Wih,
    const float* __restrict__ bih,
    const float* __restrict__ bhh,
    float4* __restrict__ out4)
{
    __shared__ float xs[NB * 34];   // [b][kk], stride 34 (8B aligned per b-row)
    __shared__ float ws[64 * 32];   // [g_local][kk]

    if (threadIdx.x < 128)
        out4[(size_t)blockIdx.x * 128 + threadIdx.x] = make_float4(0.f, 0.f, 0.f, 0.f);

    int t   = blockIdx.x >> 5;
    int g0  = (blockIdx.x & 31) << 6;
    int tid = threadIdx.x;
    int gg  = tid >> 5;
    int b   = tid & 31;

    ull acc[8];
#pragma unroll
    for (int j = 0; j < 8; j++) acc[j] = 0ull;

    const float* xt = x + (size_t)t * NB * ID;

    for (int k0 = 0; k0 < ID; k0 += 32) {
#pragma unroll
        for (int r = 0; r < 4; r++) {
            int bl = (tid >> 5) + (r << 3);
            int kk = tid & 31;
            xs[bl * 34 + kk] = xt[bl * ID + k0 + kk];
        }
#pragma unroll
        for (int r = 0; r < 8; r++) {
            int gl = (tid >> 5) + (r << 3);
            int kk = tid & 31;
            ws[gl * 32 + kk] = Wih[(size_t)(g0 + gl) * ID + k0 + kk];
        }
        __syncthreads();

#pragma unroll
        for (int kk = 0; kk < 32; kk += 4) {
            const ull* xu = (const ull*)&xs[b * 34 + kk];   // 8B aligned (34b+kk even)
            ull x01 = xu[0];
            ull x23 = xu[1];
#pragma unroll
            for (int j = 0; j < 8; j++) {
                ulonglong2 wv = *(const ulonglong2*)&ws[(gg * 8 + j) * 32 + kk];
                ffma2(acc[j], x01, wv.x);
                ffma2(acc[j], x23, wv.y);
            }
        }
        __syncthreads();
    }

    float* outp = g_xw + (size_t)t * GD * NB;
#pragma unroll
    for (int j = 0; j < 8; j++) {
        int g = g0 + gg * 8 + j;
        outp[g * NB + b] = pairsum(acc[j]) + bih[g] + bhh[g];
    }
}

// ---------------------------------------------------------------------------
// Persistent bidirectional zoneout-LSTM recurrence (R8 compute structure,
// R8 wake structure: tid0 polls + __syncthreads).
// 128 blocks: 0..63 fwd, 64..127 bwd. Block: 8 hidden units (32 gate rows) x 32 b.
// Deltas vs R8: red.release counter barrier, xw prefetch before the wait,
// c/h_old in registers.
// ---------------------------------------------------------------------------
__global__ __launch_bounds__(REC_THREADS, 1) void lstm_rec(
    const float* __restrict__ Whh, float* __restrict__ out)
{
    extern __shared__ float smem[];
    float* Wt   = smem;             // 64KB: Wt[k*32 + row]
    float* Hs   = smem + 16384;     // 64KB: Hs[u*32 + b]
    float* gbuf = smem + 32768;     // 34KB: gbuf[w*1088 + row*34 + b]

    int bid  = blockIdx.x;
    int dir  = bid >> 6;
    int j0   = (bid & 63) << 3;
    int tid  = threadIdx.x;
    int w    = tid >> 5;
    int lane = tid & 31;
    int ks0  = lane >> 4;
    int rg   = (lane >> 2) & 3;
    int bg   = lane & 3;
    int u_l  = w;               // cell phase: unit-local 0..7
    int gu   = j0 + u_l;

    // Stage W_hh once: Wt[k*32 + row], row -> global W row (row>>3)*512 + j0 + (row&7)
#pragma unroll 4
    for (int i = 0; i < 64; i++) {
        int idx = tid + (i << 8);
        int row = idx >> 9;
        int k   = idx & 511;
        int gr  = ((row >> 3) << 9) + j0 + (row & 7);
        Wt[k * 32 + row] = Whh[(size_t)gr * HD + k];
    }

    // init h(step 0) = 0 (own units); c and h_old live in registers
    float c_reg = 0.f;
    float h_reg = 0.f;
    g_hbuf[dir][0][gu * 32 + lane] = 0.f;

    // barrier base for this launch (monotonic counter, replay-safe)
    unsigned base = ld_acquire(&g_barcnt[dir]) & ~(unsigned)(NBLK_DIR - 1);

    __syncthreads();
    if (tid == 0) bar_arrive_red(dir);     // publish h0

    const float4* W4 = (const float4*)Wt;
    const float4* H4 = (const float4*)Hs;
    const int kbeg = (w << 6) + (ks0 << 5);

    for (int s = 0; s < TSEQ; s++) {
        int t = dir ? (TSEQ - 1 - s) : s;
        const float* xw_t = g_xw + (size_t)t * GD * NB;

        // prefetch xw BEFORE the wait: DRAM latency hidden under the spin
        float xg0 = xw_t[(0 * HD + gu) * NB + lane];
        float xg1 = xw_t[(1 * HD + gu) * NB + lane];
        float xg2 = xw_t[(2 * HD + gu) * NB + lane];
        float xg3 = xw_t[(3 * HD + gu) * NB + lane];

        // wait: all 64 blocks of this direction have published h_s
        if (tid == 0) bar_wait_cnt(dir, base + (unsigned)NBLK_DIR * (s + 1));
        __syncthreads();

        // per-warp copy of its own h k-range [64w, 64w+64): float4 [512w, 512w+512)
        {
            const float4* hsrc = (const float4*)g_hbuf[dir][s & 1];
            float4* hdst = (float4*)Hs;
#pragma unroll
            for (int i = 0; i < 16; i++) {
                int idx = (w << 9) + (i << 5) + lane;
                hdst[idx] = __ldcg(&hsrc[idx]);
            }
            __syncwarp();   // order cross-lane STS -> LDS within this warp
        }

        // GEMV: 8 rows x 4 batch-pairs per lane over 32 k
        ull acc[8][4];
#pragma unroll
        for (int i = 0; i < 8; i++)
#pragma unroll
            for (int j = 0; j < 4; j++) acc[i][j] = 0ull;

#pragma unroll 4
        for (int kk = 0; kk < 32; kk++) {
            int k = kbeg + kk;
            float4 wA = W4[(k << 3) + (rg << 1)];       // rows 8rg..8rg+3
            float4 wB = W4[(k << 3) + (rg << 1) + 1];   // rows 8rg+4..8rg+7
            ulonglong2 hA = *(const ulonglong2*)&H4[(k << 3) + (bg << 1)];
            ulonglong2 hB = *(const ulonglong2*)&H4[(k << 3) + (bg << 1) + 1];
            float wf[8] = {wA.x, wA.y, wA.z, wA.w, wB.x, wB.y, wB.z, wB.w};
#pragma unroll
            for (int i = 0; i < 8; i++) {
                ull wd = dup2(wf[i]);
                ffma2(acc[i][0], wd, hA.x);
                ffma2(acc[i][1], wd, hA.y);
                ffma2(acc[i][2], wd, hB.x);
                ffma2(acc[i][3], wd, hB.y);
            }
        }

        // fold k-halves + store: STATIC indices only (R7 lesson)
        {
            float* gp0 = gbuf + w * 1088 + (bg << 3) + (ks0 << 2);
#pragma unroll
            for (int i = 0; i < 8; i++) {
                ull s0 = ks0 ? acc[i][0] : acc[i][2];
                ull s1 = ks0 ? acc[i][1] : acc[i][3];
                ull r0 = __shfl_xor_sync(0xFFFFFFFFu, s0, 16);
                ull r1 = __shfl_xor_sync(0xFFFFFFFFu, s1, 16);
                ull k0 = ks0 ? acc[i][2] : acc[i][0];
                ull k1 = ks0 ? acc[i][3] : acc[i][1];
                ull v0 = addf2(k0, r0);
                ull v1 = addf2(k1, r1);
                float* gp = gp0 + ((rg << 3) + i) * 34;
                *(ull*)gp = v0;
                *(ull*)(gp + 2) = v1;
            }
        }
        __syncthreads();

        // cell update: thread = (unit u_l = w, batch lane); 8 partial sets per gate
        {
            int b = lane;
            float iv = xg0, fv = xg1, gv = xg2, ov = xg3;
#pragma unroll
            for (int sw = 0; sw < 8; sw++) {
                const float* gp = gbuf + sw * 1088 + b;
                iv += gp[(0 * 8 + u_l) * 34];
                fv += gp[(1 * 8 + u_l) * 34];
                gv += gp[(2 * 8 + u_l) * 34];
                ov += gp[(3 * 8 + u_l) * 34];
            }
            iv = sigf(iv);
            fv = sigf(fv);
            gv = tanhfast(gv);
            ov = sigf(ov);
            float c_new = fv * c_reg + iv * gv;
            float h_new = ov * tanhfast(c_new);
            c_reg = 0.9f * c_new + 0.1f * c_reg;
            float h_bl = 0.9f * h_new + 0.1f * h_reg;
            h_reg = h_bl;
            g_hbuf[dir][(s + 1) & 1][gu * 32 + lane] = h_bl;
            // fire-and-forget global add; exactly two commutative fp32 adds
            // per output element -> deterministic
            atomicAdd(&out[(size_t)t * (NB * HD) + lane * HD + gu], h_bl);
        }

        // publish h_{s+1}
        __syncthreads();
        if (tid == 0) bar_arrive_red(dir);
    }
}

// ---------------------------------------------------------------------------
extern "C" void kernel_launch(void* const* d_in, const int* in_sizes, int n_in,
                              void* d_out, int out_size) {
    const float* x   = (const float*)d_in[0];
    const float* Wih = (const float*)d_in[1];
    const float* Whh = (const float*)d_in[2];
    const float* bih = (const float*)d_in[3];
    const float* bhh = (const float*)d_in[4];
    float* out = (float*)d_out;

    const int rec_smem = (16384 + 16384 + 8 * 1088) * (int)sizeof(float); // 165888 B
    cudaFuncSetAttribute(lstm_rec, cudaFuncAttributeMaxDynamicSharedMemorySize, rec_smem);

    xw_gemm<<<TSEQ * 32, 256>>>(x, Wih, bih, bhh, (float4*)out);
    lstm_rec<<<2 * NBLK_DIR, REC_THREADS, rec_smem>>>(Whh, out);
}